// round 13
// baseline (speedup 1.0000x reference)
#include <cuda_runtime.h>

#define B 32
#define S 1024
#define W 512
#define D 768
#define NPOS 32
#define NT 192             // = D/4 threads, one float4 column per thread
#define TOTW (B * W)       // 16384 words
#define CPS 10             // CTAs per SM; reg budget ~31 at 1920 thr/SM
#define NBLK (148 * CPS)   // 1480: exactly one resident wave
#define MAXIT 12           // ceil(TOTW / NBLK)

__global__ void __launch_bounds__(NT, CPS) charpool_smeta2_kernel(
    const float* __restrict__ feats,      // [B, S, D]
    const int* __restrict__ word_lens,    // [B, W]
    const int* __restrict__ seq_len,      // [B]
    const int* __restrict__ pos,          // [B, W]
    const float* __restrict__ pos_table,  // [NPOS, D]
    float* __restrict__ out)              // [B, W, D]
{
    __shared__ int4 s_meta[MAXIT];        // {start, len, p, valid}

    const int bid = blockIdx.x;
    const int t = threadIdx.x;
    const int dq = D / 4;
    const float4* __restrict__ ptab = reinterpret_cast<const float4*>(pos_table);

    const int n = (TOTW - 1 - bid) / NBLK + 1;   // words owned by this CTA (<=12)

    // ---- one-time metadata preamble: thread j resolves word j ----
    if (t < n) {
        const int id = bid + t * NBLK;
        const int w  = id & (W - 1);
        const int b  = id >> 9;
        const int start = __ldg(&word_lens[id]);
        const int nxt   = (w + 1 < W) ? __ldg(&word_lens[id + 1]) : 0;
        const int end   = (nxt == 0) ? __ldg(&seq_len[b]) : nxt;
        int len = end - start;
        if (len < 1) len = 1;
        const int valid = (start != 0) || (w == 0);
        s_meta[t] = make_int4(start, len, __ldg(&pos[id]), valid);
    }
    __syncthreads();

    // ---- main loop: no barriers; 2-row load batch keeps live regs <= budget ----
    for (int k = 0; k < n; ++k) {
        const int4 md = s_meta[k];                 // start, len, p, valid
        const int id = bid + k * NBLK;

        const float4 pt = ptab[md.z * dq + t];
        float4 r;

        if (md.w) {
            const int len = md.y;
            const float4* fp = reinterpret_cast<const float4*>(
                feats + ((size_t)(id >> 9) * S + (size_t)md.x) * D) + t;

            float4 acc = make_float4(0.f, 0.f, 0.f, 0.f);
            const float4 z = make_float4(0.f, 0.f, 0.f, 0.f);
            for (int s = 0; s < len; s += 2) {
                float4 v0 = fp[0 * dq];
                float4 v1 = (s + 1 < len) ? fp[1 * dq] : z;
                acc.x += v0.x + v1.x;
                acc.y += v0.y + v1.y;
                acc.z += v0.z + v1.z;
                acc.w += v0.w + v1.w;
                fp += 2 * dq;
            }
            const float inv = 1.0f / (float)len;
            r.x = fmaf(acc.x, inv, pt.x);
            r.y = fmaf(acc.y, inv, pt.y);
            r.z = fmaf(acc.z, inv, pt.z);
            r.w = fmaf(acc.w, inv, pt.w);
        } else {
            r = pt;   // pos=0 table row is zero -> zeros for padding words
        }

        // streaming store: out has zero reuse; don't displace L2-resident feats
        __stcs(reinterpret_cast<float4*>(out + (size_t)id * D) + t, r);
    }
}

extern "C" void kernel_launch(void* const* d_in, const int* in_sizes, int n_in,
                              void* d_out, int out_size)
{
    const float* feats     = (const float*)d_in[0];
    const int*   word_lens = (const int*)d_in[1];
    const int*   seq_len   = (const int*)d_in[2];
    const int*   pos       = (const int*)d_in[3];
    const float* pos_table = (const float*)d_in[4];
    float* out = (float*)d_out;

    charpool_smeta2_kernel<<<NBLK, NT>>>(feats, word_lens, seq_len, pos, pos_table, out);
}

// round 14
// speedup vs baseline: 1.0579x; 1.0579x over previous
#include <cuda_runtime.h>

#define B 32
#define S 1024
#define W 512
#define D 768
#define NPOS 32
#define NT 192             // = D/4 threads, one float4 column per thread
#define TOTW (B * W)       // 16384 words
#define CPS 9              // CTAs per SM; reg budget 37 at 1728 thr/SM
#define NBLK (148 * CPS)   // 1332: exactly one resident wave
#define MAXIT 13           // ceil(TOTW / NBLK)

__global__ void __launch_bounds__(NT, CPS) charpool_smeta9_kernel(
    const float* __restrict__ feats,      // [B, S, D]
    const int* __restrict__ word_lens,    // [B, W]
    const int* __restrict__ seq_len,      // [B]
    const int* __restrict__ pos,          // [B, W]
    const float* __restrict__ pos_table,  // [NPOS, D]
    float* __restrict__ out)              // [B, W, D]
{
    __shared__ int4 s_meta[MAXIT];        // {start, len, p, valid}

    const int bid = blockIdx.x;
    const int t = threadIdx.x;
    const int dq = D / 4;
    const float4* __restrict__ ptab = reinterpret_cast<const float4*>(pos_table);

    const int n = (TOTW - 1 - bid) / NBLK + 1;   // words owned by this CTA (<=13)

    // ---- one-time metadata preamble: thread j resolves word j ----
    if (t < n) {
        const int id = bid + t * NBLK;
        const int w  = id & (W - 1);
        const int b  = id >> 9;
        const int start = __ldg(&word_lens[id]);
        const int nxt   = (w + 1 < W) ? __ldg(&word_lens[id + 1]) : 0;
        const int end   = (nxt == 0) ? __ldg(&seq_len[b]) : nxt;
        int len = end - start;
        if (len < 1) len = 1;
        const int valid = (start != 0) || (w == 0);
        s_meta[t] = make_int4(start, len, __ldg(&pos[id]), valid);
    }
    __syncthreads();

    // ---- main loop: no barriers; 2-row load batch keeps live regs <= budget ----
    for (int k = 0; k < n; ++k) {
        const int4 md = s_meta[k];                 // start, len, p, valid
        const int id = bid + k * NBLK;

        const float4 pt = ptab[md.z * dq + t];
        float4 r;

        if (md.w) {
            const int len = md.y;
            const float4* fp = reinterpret_cast<const float4*>(
                feats + ((size_t)(id >> 9) * S + (size_t)md.x) * D) + t;

            float4 acc = make_float4(0.f, 0.f, 0.f, 0.f);
            const float4 z = make_float4(0.f, 0.f, 0.f, 0.f);
            for (int s = 0; s < len; s += 2) {
                float4 v0 = fp[0 * dq];
                float4 v1 = (s + 1 < len) ? fp[1 * dq] : z;
                acc.x += v0.x + v1.x;
                acc.y += v0.y + v1.y;
                acc.z += v0.z + v1.z;
                acc.w += v0.w + v1.w;
                fp += 2 * dq;
            }
            const float inv = 1.0f / (float)len;
            r.x = fmaf(acc.x, inv, pt.x);
            r.y = fmaf(acc.y, inv, pt.y);
            r.z = fmaf(acc.z, inv, pt.z);
            r.w = fmaf(acc.w, inv, pt.w);
        } else {
            r = pt;   // pos=0 table row is zero -> zeros for padding words
        }

        // streaming store: out has zero reuse; don't displace L2-resident feats
        __stcs(reinterpret_cast<float4*>(out + (size_t)id * D) + t, r);
    }
}

extern "C" void kernel_launch(void* const* d_in, const int* in_sizes, int n_in,
                              void* d_out, int out_size)
{
    const float* feats     = (const float*)d_in[0];
    const int*   word_lens = (const int*)d_in[1];
    const int*   seq_len   = (const int*)d_in[2];
    const int*   pos       = (const int*)d_in[3];
    const float* pos_table = (const float*)d_in[4];
    float* out = (float*)d_out;

    charpool_smeta9_kernel<<<NBLK, NT>>>(feats, word_lens, seq_len, pos, pos_table, out);
}

// round 16
// speedup vs baseline: 1.4681x; 1.3878x over previous
#include <cuda_runtime.h>

#define B 32
#define S 1024
#define W 512
#define D 768
#define NPOS 32
#define NT 192             // = D/4 threads, one float4 column per thread
#define TOTW (B * W)       // 16384 words
#define CPS 8              // CTAs per SM (reg budget 40: fits without spill)
#define NBLK (148 * CPS * 2)  // 2368: exactly two resident waves -> self-balancing

__global__ void __launch_bounds__(NT, CPS) charpool_2wave_kernel(
    const float* __restrict__ feats,      // [B, S, D]
    const int* __restrict__ word_lens,    // [B, W]
    const int* __restrict__ seq_len,      // [B]
    const int* __restrict__ pos,          // [B, W]
    const float* __restrict__ pos_table,  // [NPOS, D]
    float* __restrict__ out)              // [B, W, D]
{
    const int t = threadIdx.x;
    const int dq = D / 4;
    const float4* __restrict__ ptab = reinterpret_cast<const float4*>(pos_table);

    int id = blockIdx.x;
    if (id >= TOTW) return;

    // metadata for first word
    int start = __ldg(&word_lens[id]);
    int nxt   = ((id & (W - 1)) + 1 < W) ? __ldg(&word_lens[id + 1]) : 0;
    int p     = __ldg(&pos[id]);
    int sl    = __ldg(&seq_len[id >> 9]);

    for (;;) {
        // ---- prefetch next word's metadata (overlaps current feats latency) ----
        const int nid  = id + NBLK;
        const bool more = (nid < TOTW);
        int n_start = 0, n_nxt = 0, n_p = 0, n_sl = 0;
        if (more) {
            n_start = __ldg(&word_lens[nid]);
            n_nxt   = ((nid & (W - 1)) + 1 < W) ? __ldg(&word_lens[nid + 1]) : 0;
            n_p     = __ldg(&pos[nid]);
            n_sl    = __ldg(&seq_len[nid >> 9]);
        }

        // ---- process current word ----
        const int b   = id >> 9;
        const int w   = id & (W - 1);
        const int end = (nxt == 0) ? sl : nxt;
        const bool valid = (start != 0) || (w == 0);

        const float4 pt = ptab[p * dq + t];
        float4 r;

        if (valid) {
            int len = end - start;
            if (len < 1) len = 1;
            const float4* fp = reinterpret_cast<const float4*>(
                feats + ((size_t)b * S + (size_t)start) * D) + t;

            float4 acc = make_float4(0.f, 0.f, 0.f, 0.f);
            const float4 z = make_float4(0.f, 0.f, 0.f, 0.f);
            for (int s = 0; s < len; s += 4) {
                // up to 4 independent row loads issued before any consume
                float4 v0 = fp[0 * dq];
                float4 v1 = (s + 1 < len) ? fp[1 * dq] : z;
                float4 v2 = (s + 2 < len) ? fp[2 * dq] : z;
                float4 v3 = (s + 3 < len) ? fp[3 * dq] : z;
                acc.x += (v0.x + v1.x) + (v2.x + v3.x);
                acc.y += (v0.y + v1.y) + (v2.y + v3.y);
                acc.z += (v0.z + v1.z) + (v2.z + v3.z);
                acc.w += (v0.w + v1.w) + (v2.w + v3.w);
                fp += 4 * dq;
            }
            const float inv = 1.0f / (float)len;
            r.x = fmaf(acc.x, inv, pt.x);
            r.y = fmaf(acc.y, inv, pt.y);
            r.z = fmaf(acc.z, inv, pt.z);
            r.w = fmaf(acc.w, inv, pt.w);
        } else {
            r = pt;  // pos=0 row of the table is zero -> zeros for padding words
        }

        // streaming store: out has zero reuse; don't displace L2-resident feats
        __stcs(reinterpret_cast<float4*>(out + (size_t)id * D) + t, r);

        if (!more) break;
        id = nid;
        start = n_start; nxt = n_nxt; p = n_p; sl = n_sl;
    }
}

extern "C" void kernel_launch(void* const* d_in, const int* in_sizes, int n_in,
                              void* d_out, int out_size)
{
    const float* feats     = (const float*)d_in[0];
    const int*   word_lens = (const int*)d_in[1];
    const int*   seq_len   = (const int*)d_in[2];
    const int*   pos       = (const int*)d_in[3];
    const float* pos_table = (const float*)d_in[4];
    float* out = (float*)d_out;

    charpool_2wave_kernel<<<NBLK, NT>>>(feats, word_lens, seq_len, pos, pos_table, out);
}